// round 1
// baseline (speedup 1.0000x reference)
#include <cuda_runtime.h>
#include <cuda_bf16.h>
#include <math.h>

#define T     1024
#define HDIM  1024
#define NEXP  16
#define IDIM  512
#define ISDIM 2048
#define TOPK  4

#define BM 64
#define BN 64
#define BK 16

// ---------------- scratch (device globals; no allocation allowed) ----------
__device__ int   g_counts[NEXP];
__device__ int   g_tok[NEXP * T];          // token index per (expert, pos)
__device__ float g_wt[NEXP * T];           // routing weight per (expert, pos)
__device__ int   g_slot[T * TOPK];         // per token: 4 slot ids (e*T+pos)
__device__ float g_sg[T];                  // sigmoid shared gate per token
__device__ float g_act[(size_t)NEXP * T * IDIM];   // expert silu(g)*u   (32 MB)
__device__ float g_acts[(size_t)T * ISDIM];        // shared silu(g)*u   (8 MB)
__device__ float g_down[(size_t)NEXP * T * HDIM];  // per-slot weighted down (64 MB)

// ---------------- kernel 0: zero counts ------------------------------------
__global__ void zero_counts_kernel() {
    if (threadIdx.x < NEXP) g_counts[threadIdx.x] = 0;
}

// ---------------- kernel 1: router ------------------------------------------
// grid = T blocks, 512 threads (16 warps). Warp e computes logit e; warp 0
// also computes the shared sigmoid gate. Thread 0 does softmax/top4/scatter.
__global__ void router_kernel(const float* __restrict__ x,
                              const float* __restrict__ wr,
                              const float* __restrict__ wsg,
                              float* __restrict__ logits_out) {
    int t    = blockIdx.x;
    int warp = threadIdx.x >> 5;
    int lane = threadIdx.x & 31;
    __shared__ float s_logit[NEXP];

    const float* xr = x + (size_t)t * HDIM;

    {   // logits
        float acc = 0.f;
        for (int h = lane; h < HDIM; h += 32)
            acc += xr[h] * wr[h * NEXP + warp];
        #pragma unroll
        for (int o = 16; o; o >>= 1) acc += __shfl_xor_sync(0xffffffffu, acc, o);
        if (lane == 0) {
            s_logit[warp] = acc;
            logits_out[t * NEXP + warp] = acc;
        }
    }
    if (warp == 0) {    // shared sigmoid gate
        float acc = 0.f;
        for (int h = lane; h < HDIM; h += 32) acc += xr[h] * wsg[h];
        #pragma unroll
        for (int o = 16; o; o >>= 1) acc += __shfl_xor_sync(0xffffffffu, acc, o);
        if (lane == 0) g_sg[t] = 1.f / (1.f + expf(-acc));
    }
    __syncthreads();

    if (threadIdx.x == 0) {
        float p[NEXP];
        float mx = -1e30f;
        #pragma unroll
        for (int e = 0; e < NEXP; e++) mx = fmaxf(mx, s_logit[e]);
        float sum = 0.f;
        #pragma unroll
        for (int e = 0; e < NEXP; e++) { p[e] = expf(s_logit[e] - mx); sum += p[e]; }
        float inv = 1.f / sum;
        #pragma unroll
        for (int e = 0; e < NEXP; e++) p[e] *= inv;

        int   idx[TOPK];
        float w[TOPK];
        float wsum = 0.f;
        #pragma unroll
        for (int k = 0; k < TOPK; k++) {
            int best = 0; float bv = -1.f;
            #pragma unroll
            for (int e = 0; e < NEXP; e++)
                if (p[e] > bv) { bv = p[e]; best = e; }
            idx[k] = best; w[k] = bv; wsum += bv; p[best] = -2.f;
        }
        float winv = 1.f / wsum;
        #pragma unroll
        for (int k = 0; k < TOPK; k++) {
            int e = idx[k];
            int pos = atomicAdd(&g_counts[e], 1);
            g_tok[e * T + pos] = t;
            g_wt[e * T + pos]  = w[k] * winv;
            g_slot[t * TOPK + k] = e * T + pos;
        }
    }
}

// ---------------- kernel 2: expert gate/up fused GEMM -----------------------
// C_act[e, row, n] = silu(A·Wg) * (A·Wu), A rows gathered via g_tok.
// grid = (IDIM/BN, T/BM, NEXP), 256 threads.
__global__ __launch_bounds__(256)
void gateup_expert_kernel(const float* __restrict__ x,
                          const float* __restrict__ wg,
                          const float* __restrict__ wu) {
    int e     = blockIdx.z;
    int count = g_counts[e];
    int m0    = blockIdx.y * BM;
    if (m0 >= count) return;
    int n0 = blockIdx.x * BN;

    const float* Bg = wg + (size_t)e * HDIM * IDIM;
    const float* Bu = wu + (size_t)e * HDIM * IDIM;

    __shared__ float As [BK][BM + 4];
    __shared__ float Bgs[BK][BN];
    __shared__ float Bus[BK][BN];

    int tid = threadIdx.x;
    int tx = tid & 15, ty = tid >> 4;

    int am = tid >> 2;
    int ak = (tid & 3) * 4;
    int row = m0 + am;
    const float* arow = (row < count) ? (x + (size_t)g_tok[e * T + row] * HDIM)
                                      : nullptr;
    int bk = tid >> 4;
    int bn = (tid & 15) * 4;

    float accg[4][4] = {};
    float accu[4][4] = {};

    for (int k0 = 0; k0 < HDIM; k0 += BK) {
        float4 av = arow ? *(const float4*)(arow + k0 + ak)
                         : make_float4(0.f, 0.f, 0.f, 0.f);
        As[ak + 0][am] = av.x; As[ak + 1][am] = av.y;
        As[ak + 2][am] = av.z; As[ak + 3][am] = av.w;
        *(float4*)&Bgs[bk][bn] = *(const float4*)(Bg + (size_t)(k0 + bk) * IDIM + n0 + bn);
        *(float4*)&Bus[bk][bn] = *(const float4*)(Bu + (size_t)(k0 + bk) * IDIM + n0 + bn);
        __syncthreads();
        #pragma unroll
        for (int k = 0; k < BK; k++) {
            float4 a  = *(const float4*)&As [k][ty * 4];
            float4 bg = *(const float4*)&Bgs[k][tx * 4];
            float4 bu = *(const float4*)&Bus[k][tx * 4];
            float aa[4] = {a.x, a.y, a.z, a.w};
            float gg[4] = {bg.x, bg.y, bg.z, bg.w};
            float uu[4] = {bu.x, bu.y, bu.z, bu.w};
            #pragma unroll
            for (int i = 0; i < 4; i++)
                #pragma unroll
                for (int j = 0; j < 4; j++) {
                    accg[i][j] = fmaf(aa[i], gg[j], accg[i][j]);
                    accu[i][j] = fmaf(aa[i], uu[j], accu[i][j]);
                }
        }
        __syncthreads();
    }

    float* Cb = g_act + (size_t)e * T * IDIM;
    #pragma unroll
    for (int i = 0; i < 4; i++) {
        int r = m0 + ty * 4 + i;
        if (r >= count) continue;
        #pragma unroll
        for (int j = 0; j < 4; j++) {
            float g = accg[i][j], u = accu[i][j];
            float s = g / (1.f + expf(-g));
            Cb[(size_t)r * IDIM + n0 + tx * 4 + j] = s * u;
        }
    }
}

// ---------------- kernel 3: shared-expert gate/up GEMM ----------------------
// grid = (ISDIM/BN, T/BM)
__global__ __launch_bounds__(256)
void gateup_shared_kernel(const float* __restrict__ x,
                          const float* __restrict__ wsg,
                          const float* __restrict__ wsu) {
    int m0 = blockIdx.y * BM;
    int n0 = blockIdx.x * BN;

    __shared__ float As [BK][BM + 4];
    __shared__ float Bgs[BK][BN];
    __shared__ float Bus[BK][BN];

    int tid = threadIdx.x;
    int tx = tid & 15, ty = tid >> 4;
    int am = tid >> 2;
    int ak = (tid & 3) * 4;
    const float* arow = x + (size_t)(m0 + am) * HDIM;
    int bk = tid >> 4;
    int bn = (tid & 15) * 4;

    float accg[4][4] = {};
    float accu[4][4] = {};

    for (int k0 = 0; k0 < HDIM; k0 += BK) {
        float4 av = *(const float4*)(arow + k0 + ak);
        As[ak + 0][am] = av.x; As[ak + 1][am] = av.y;
        As[ak + 2][am] = av.z; As[ak + 3][am] = av.w;
        *(float4*)&Bgs[bk][bn] = *(const float4*)(wsg + (size_t)(k0 + bk) * ISDIM + n0 + bn);
        *(float4*)&Bus[bk][bn] = *(const float4*)(wsu + (size_t)(k0 + bk) * ISDIM + n0 + bn);
        __syncthreads();
        #pragma unroll
        for (int k = 0; k < BK; k++) {
            float4 a  = *(const float4*)&As [k][ty * 4];
            float4 bg = *(const float4*)&Bgs[k][tx * 4];
            float4 bu = *(const float4*)&Bus[k][tx * 4];
            float aa[4] = {a.x, a.y, a.z, a.w};
            float gg[4] = {bg.x, bg.y, bg.z, bg.w};
            float uu[4] = {bu.x, bu.y, bu.z, bu.w};
            #pragma unroll
            for (int i = 0; i < 4; i++)
                #pragma unroll
                for (int j = 0; j < 4; j++) {
                    accg[i][j] = fmaf(aa[i], gg[j], accg[i][j]);
                    accu[i][j] = fmaf(aa[i], uu[j], accu[i][j]);
                }
        }
        __syncthreads();
    }

    #pragma unroll
    for (int i = 0; i < 4; i++) {
        int r = m0 + ty * 4 + i;
        #pragma unroll
        for (int j = 0; j < 4; j++) {
            float g = accg[i][j], u = accu[i][j];
            float s = g / (1.f + expf(-g));
            g_acts[(size_t)r * ISDIM + n0 + tx * 4 + j] = s * u;
        }
    }
}

// ---------------- kernel 4: expert down GEMM --------------------------------
// g_down[slot, h] = wt[slot] * (act[slot] · Wd_e).  grid = (HDIM/BN, T/BM, NEXP)
__global__ __launch_bounds__(256)
void down_expert_kernel(const float* __restrict__ wd) {
    int e     = blockIdx.z;
    int count = g_counts[e];
    int m0    = blockIdx.y * BM;
    if (m0 >= count) return;
    int n0 = blockIdx.x * BN;

    const float* A = g_act + (size_t)e * T * IDIM;
    const float* B = wd    + (size_t)e * IDIM * HDIM;

    __shared__ float As[BK][BM + 4];
    __shared__ float Bs[BK][BN];

    int tid = threadIdx.x;
    int tx = tid & 15, ty = tid >> 4;
    int am = tid >> 2;
    int ak = (tid & 3) * 4;
    const float* arow = A + (size_t)(m0 + am) * IDIM;   // stale rows guarded at store
    int bk = tid >> 4;
    int bn = (tid & 15) * 4;

    float acc[4][4] = {};

    for (int k0 = 0; k0 < IDIM; k0 += BK) {
        float4 av = *(const float4*)(arow + k0 + ak);
        As[ak + 0][am] = av.x; As[ak + 1][am] = av.y;
        As[ak + 2][am] = av.z; As[ak + 3][am] = av.w;
        *(float4*)&Bs[bk][bn] = *(const float4*)(B + (size_t)(k0 + bk) * HDIM + n0 + bn);
        __syncthreads();
        #pragma unroll
        for (int k = 0; k < BK; k++) {
            float4 a = *(const float4*)&As[k][ty * 4];
            float4 b = *(const float4*)&Bs[k][tx * 4];
            float aa[4] = {a.x, a.y, a.z, a.w};
            float bb[4] = {b.x, b.y, b.z, b.w};
            #pragma unroll
            for (int i = 0; i < 4; i++)
                #pragma unroll
                for (int j = 0; j < 4; j++)
                    acc[i][j] = fmaf(aa[i], bb[j], acc[i][j]);
        }
        __syncthreads();
    }

    #pragma unroll
    for (int i = 0; i < 4; i++) {
        int r = m0 + ty * 4 + i;
        if (r >= count) continue;
        float w = g_wt[e * T + r];
        float* dst = g_down + (size_t)(e * T + r) * HDIM + n0 + tx * 4;
        #pragma unroll
        for (int j = 0; j < 4; j++) dst[j] = w * acc[i][j];
    }
}

// ---------------- kernel 5: shared down GEMM + combine ----------------------
// out[t,h] = sg[t]*(acts[t]·Wsd)[h] + sum_k g_down[slot_k(t), h]
// grid = (HDIM/BN, T/BM)
__global__ __launch_bounds__(256)
void shared_down_combine_kernel(const float* __restrict__ wsd,
                                float* __restrict__ out) {
    int m0 = blockIdx.y * BM;
    int n0 = blockIdx.x * BN;

    __shared__ float As[BK][BM + 4];
    __shared__ float Bs[BK][BN];

    int tid = threadIdx.x;
    int tx = tid & 15, ty = tid >> 4;
    int am = tid >> 2;
    int ak = (tid & 3) * 4;
    const float* arow = g_acts + (size_t)(m0 + am) * ISDIM;
    int bk = tid >> 4;
    int bn = (tid & 15) * 4;

    float acc[4][4] = {};

    for (int k0 = 0; k0 < ISDIM; k0 += BK) {
        float4 av = *(const float4*)(arow + k0 + ak);
        As[ak + 0][am] = av.x; As[ak + 1][am] = av.y;
        As[ak + 2][am] = av.z; As[ak + 3][am] = av.w;
        *(float4*)&Bs[bk][bn] = *(const float4*)(wsd + (size_t)(k0 + bk) * HDIM + n0 + bn);
        __syncthreads();
        #pragma unroll
        for (int k = 0; k < BK; k++) {
            float4 a = *(const float4*)&As[k][ty * 4];
            float4 b = *(const float4*)&Bs[k][tx * 4];
            float aa[4] = {a.x, a.y, a.z, a.w};
            float bb[4] = {b.x, b.y, b.z, b.w};
            #pragma unroll
            for (int i = 0; i < 4; i++)
                #pragma unroll
                for (int j = 0; j < 4; j++)
                    acc[i][j] = fmaf(aa[i], bb[j], acc[i][j]);
        }
        __syncthreads();
    }

    #pragma unroll
    for (int i = 0; i < 4; i++) {
        int t = m0 + ty * 4 + i;
        float sg = g_sg[t];
        int s0 = g_slot[t * TOPK + 0];
        int s1 = g_slot[t * TOPK + 1];
        int s2 = g_slot[t * TOPK + 2];
        int s3 = g_slot[t * TOPK + 3];
        int col = n0 + tx * 4;
        float4 d0 = *(const float4*)(g_down + (size_t)s0 * HDIM + col);
        float4 d1 = *(const float4*)(g_down + (size_t)s1 * HDIM + col);
        float4 d2 = *(const float4*)(g_down + (size_t)s2 * HDIM + col);
        float4 d3 = *(const float4*)(g_down + (size_t)s3 * HDIM + col);
        float4 res;
        res.x = sg * acc[i][0] + d0.x + d1.x + d2.x + d3.x;
        res.y = sg * acc[i][1] + d0.y + d1.y + d2.y + d3.y;
        res.z = sg * acc[i][2] + d0.z + d1.z + d2.z + d3.z;
        res.w = sg * acc[i][3] + d0.w + d1.w + d2.w + d3.w;
        *(float4*)(out + (size_t)t * HDIM + col) = res;
    }
}

// ---------------- launch -----------------------------------------------------
extern "C" void kernel_launch(void* const* d_in, const int* in_sizes, int n_in,
                              void* d_out, int out_size) {
    const float* x    = (const float*)d_in[0];   // [1,1024,1024]
    const float* wr   = (const float*)d_in[1];   // [1024,16]
    const float* wg   = (const float*)d_in[2];   // [16,1024,512]
    const float* wu   = (const float*)d_in[3];   // [16,1024,512]
    const float* wd   = (const float*)d_in[4];   // [16,512,1024]
    const float* wsg  = (const float*)d_in[5];   // [1024,2048]
    const float* wsu  = (const float*)d_in[6];   // [1024,2048]
    const float* wsd  = (const float*)d_in[7];   // [2048,1024]
    const float* wshg = (const float*)d_in[8];   // [1024,1]
    float* out = (float*)d_out;                  // [out (T*H) | router_logits (T*E)]

    zero_counts_kernel<<<1, 32>>>();
    router_kernel<<<T, 512>>>(x, wr, wshg, out + (size_t)T * HDIM);
    gateup_expert_kernel<<<dim3(IDIM / BN, T / BM, NEXP), 256>>>(x, wg, wu);
    gateup_shared_kernel<<<dim3(ISDIM / BN, T / BM), 256>>>(x, wsg, wsu);
    down_expert_kernel<<<dim3(HDIM / BN, T / BM, NEXP), 256>>>(wd);
    shared_down_combine_kernel<<<dim3(HDIM / BN, T / BM), 256>>>(wsd, out);
}

// round 2
// speedup vs baseline: 1.8905x; 1.8905x over previous
#include <cuda_runtime.h>
#include <cuda_bf16.h>
#include <math.h>

#define T     1024
#define HDIM  1024
#define NEXP  16
#define IDIM  512
#define ISDIM 2048
#define TOPK  4

// ---------------- scratch (device globals; no allocation allowed) ----------
__device__ int   g_counts[NEXP];
__device__ int   g_tok[NEXP * T];          // token index per (expert, pos)
__device__ float g_wt[NEXP * T];           // routing weight per (expert, pos)
__device__ int   g_slot[T * TOPK];         // per token: 4 slot ids (e*T+pos)
__device__ float g_sg[T];                  // sigmoid shared gate per token
__device__ float g_act[(size_t)NEXP * T * IDIM];   // expert silu(g)*u
__device__ float g_acts[(size_t)T * ISDIM];        // shared silu(g)*u
__device__ float g_down[(size_t)NEXP * T * HDIM];  // per-slot weighted down

// ---------------- helpers ----------------------------------------------------
__device__ __forceinline__ float to_tf32(float x) {
    unsigned u;
    asm("cvt.rna.tf32.f32 %0, %1;" : "=r"(u) : "f"(x));
    return __uint_as_float(u);
}

__device__ __forceinline__ void mma_tf32(float* d, const float* a, const float* b) {
    asm volatile(
        "mma.sync.aligned.m16n8k8.row.col.f32.tf32.tf32.f32 "
        "{%0,%1,%2,%3}, {%4,%5,%6,%7}, {%8,%9}, {%0,%1,%2,%3};\n"
        : "+f"(d[0]), "+f"(d[1]), "+f"(d[2]), "+f"(d[3])
        : "r"(__float_as_uint(a[0])), "r"(__float_as_uint(a[1])),
          "r"(__float_as_uint(a[2])), "r"(__float_as_uint(a[3])),
          "r"(__float_as_uint(b[0])), "r"(__float_as_uint(b[1])));
}

__device__ __forceinline__ float silu(float g) { return g / (1.f + expf(-g)); }

// ---------------- kernel 0: zero counts ------------------------------------
__global__ void zero_counts_kernel() {
    if (threadIdx.x < NEXP) g_counts[threadIdx.x] = 0;
}

// ---------------- kernel 1: router ------------------------------------------
__global__ void router_kernel(const float* __restrict__ x,
                              const float* __restrict__ wr,
                              const float* __restrict__ wsg,
                              float* __restrict__ logits_out) {
    int t    = blockIdx.x;
    int warp = threadIdx.x >> 5;
    int lane = threadIdx.x & 31;
    __shared__ float s_logit[NEXP];

    const float* xr = x + (size_t)t * HDIM;

    {   // logits
        float acc = 0.f;
        for (int h = lane; h < HDIM; h += 32)
            acc += xr[h] * wr[h * NEXP + warp];
        #pragma unroll
        for (int o = 16; o; o >>= 1) acc += __shfl_xor_sync(0xffffffffu, acc, o);
        if (lane == 0) {
            s_logit[warp] = acc;
            logits_out[t * NEXP + warp] = acc;
        }
    }
    if (warp == 0) {    // shared sigmoid gate
        float acc = 0.f;
        for (int h = lane; h < HDIM; h += 32) acc += xr[h] * wsg[h];
        #pragma unroll
        for (int o = 16; o; o >>= 1) acc += __shfl_xor_sync(0xffffffffu, acc, o);
        if (lane == 0) g_sg[t] = 1.f / (1.f + expf(-acc));
    }
    __syncthreads();

    if (threadIdx.x == 0) {
        float p[NEXP];
        float mx = -1e30f;
        #pragma unroll
        for (int e = 0; e < NEXP; e++) mx = fmaxf(mx, s_logit[e]);
        float sum = 0.f;
        #pragma unroll
        for (int e = 0; e < NEXP; e++) { p[e] = expf(s_logit[e] - mx); sum += p[e]; }
        float inv = 1.f / sum;
        #pragma unroll
        for (int e = 0; e < NEXP; e++) p[e] *= inv;

        int   idx[TOPK];
        float w[TOPK];
        float wsum = 0.f;
        #pragma unroll
        for (int k = 0; k < TOPK; k++) {
            int best = 0; float bv = -1.f;
            #pragma unroll
            for (int e = 0; e < NEXP; e++)
                if (p[e] > bv) { bv = p[e]; best = e; }
            idx[k] = best; w[k] = bv; wsum += bv; p[best] = -2.f;
        }
        float winv = 1.f / wsum;
        #pragma unroll
        for (int k = 0; k < TOPK; k++) {
            int e = idx[k];
            int pos = atomicAdd(&g_counts[e], 1);
            g_tok[e * T + pos] = t;
            g_wt[e * T + pos]  = w[k] * winv;
            g_slot[t * TOPK + k] = e * T + pos;
        }
    }
}

// ============================================================================
// TF32 tensor-core GEMM kernels
// Tile: BM=64, BN=64, BK=32. 128 threads = 4 warps in 2x2; warp tile 32x32
// (2 m16-tiles x 4 n8-tiles of m16n8k8). A smem stride 36, B stride 68 ->
// conflict-free fragment loads. tf32 rounding applied at smem fill.
// ============================================================================

// ---------------- kernel 2: expert gate/up fused (M=count_e, N=512, K=1024) -
__global__ __launch_bounds__(128)
void gateup_expert_tc(const float* __restrict__ x,
                      const float* __restrict__ wg,
                      const float* __restrict__ wu) {
    int e     = blockIdx.z;
    int count = g_counts[e];
    int m0    = blockIdx.y * 64;
    if (m0 >= count) return;
    int n0 = blockIdx.x * 64;

    const float* Bgp = wg + (size_t)e * HDIM * IDIM;
    const float* Bup = wu + (size_t)e * HDIM * IDIM;

    __shared__ float As[64][36];
    __shared__ float Bgs[32][68];
    __shared__ float Bus[32][68];

    int tid = threadIdx.x, lane = tid & 31, warp = tid >> 5;
    int wm = (warp >> 1) * 32, wn = (warp & 1) * 32;
    int r = lane >> 2, c = lane & 3;

    int arow = tid >> 3, ac4 = tid & 7;
    int bkr = tid >> 2, bc4 = tid & 3;

    // resolve gathered A row pointers once
    const float* aptr[4];
    #pragma unroll
    for (int it = 0; it < 4; it++) {
        int row = m0 + arow + it * 16;
        aptr[it] = (row < count) ? (x + (size_t)g_tok[e * T + row] * HDIM) : nullptr;
    }

    float ag[2][4][4] = {};
    float au[2][4][4] = {};

    for (int k0 = 0; k0 < HDIM; k0 += 32) {
        #pragma unroll
        for (int it = 0; it < 4; it++) {
            float4 v = aptr[it] ? *(const float4*)(aptr[it] + k0 + ac4 * 4)
                                : make_float4(0.f, 0.f, 0.f, 0.f);
            v.x = to_tf32(v.x); v.y = to_tf32(v.y);
            v.z = to_tf32(v.z); v.w = to_tf32(v.w);
            *(float4*)&As[arow + it * 16][ac4 * 4] = v;
        }
        #pragma unroll
        for (int it = 0; it < 4; it++) {
            int cc = (bc4 + it * 4) * 4;
            float4 vg = *(const float4*)(Bgp + (size_t)(k0 + bkr) * IDIM + n0 + cc);
            float4 vu = *(const float4*)(Bup + (size_t)(k0 + bkr) * IDIM + n0 + cc);
            vg.x = to_tf32(vg.x); vg.y = to_tf32(vg.y); vg.z = to_tf32(vg.z); vg.w = to_tf32(vg.w);
            vu.x = to_tf32(vu.x); vu.y = to_tf32(vu.y); vu.z = to_tf32(vu.z); vu.w = to_tf32(vu.w);
            *(float4*)&Bgs[bkr][cc] = vg;
            *(float4*)&Bus[bkr][cc] = vu;
        }
        __syncthreads();
        #pragma unroll
        for (int ks = 0; ks < 32; ks += 8) {
            float a[2][4];
            #pragma unroll
            for (int mt = 0; mt < 2; mt++) {
                int rb = wm + mt * 16 + r;
                a[mt][0] = As[rb][ks + c];
                a[mt][1] = As[rb + 8][ks + c];
                a[mt][2] = As[rb][ks + c + 4];
                a[mt][3] = As[rb + 8][ks + c + 4];
            }
            #pragma unroll
            for (int nt = 0; nt < 4; nt++) {
                int cb = wn + nt * 8 + r;
                float bg[2] = { Bgs[ks + c][cb], Bgs[ks + c + 4][cb] };
                float bu[2] = { Bus[ks + c][cb], Bus[ks + c + 4][cb] };
                #pragma unroll
                for (int mt = 0; mt < 2; mt++) {
                    mma_tf32(ag[mt][nt], a[mt], bg);
                    mma_tf32(au[mt][nt], a[mt], bu);
                }
            }
        }
        __syncthreads();
    }

    float* Cb = g_act + (size_t)e * T * IDIM;
    #pragma unroll
    for (int mt = 0; mt < 2; mt++) {
        int row0 = m0 + wm + mt * 16 + r;
        #pragma unroll
        for (int nt = 0; nt < 4; nt++) {
            int col = n0 + wn + nt * 8 + c * 2;
            if (row0 < count) {
                float2 o;
                o.x = silu(ag[mt][nt][0]) * au[mt][nt][0];
                o.y = silu(ag[mt][nt][1]) * au[mt][nt][1];
                *(float2*)(Cb + (size_t)row0 * IDIM + col) = o;
            }
            if (row0 + 8 < count) {
                float2 o;
                o.x = silu(ag[mt][nt][2]) * au[mt][nt][2];
                o.y = silu(ag[mt][nt][3]) * au[mt][nt][3];
                *(float2*)(Cb + (size_t)(row0 + 8) * IDIM + col) = o;
            }
        }
    }
}

// ---------------- kernel 3: shared gate/up (M=1024, N=2048, K=1024) ---------
__global__ __launch_bounds__(128)
void gateup_shared_tc(const float* __restrict__ x,
                      const float* __restrict__ wsg,
                      const float* __restrict__ wsu) {
    int m0 = blockIdx.y * 64;
    int n0 = blockIdx.x * 64;

    __shared__ float As[64][36];
    __shared__ float Bgs[32][68];
    __shared__ float Bus[32][68];

    int tid = threadIdx.x, lane = tid & 31, warp = tid >> 5;
    int wm = (warp >> 1) * 32, wn = (warp & 1) * 32;
    int r = lane >> 2, c = lane & 3;

    int arow = tid >> 3, ac4 = tid & 7;
    int bkr = tid >> 2, bc4 = tid & 3;

    float ag[2][4][4] = {};
    float au[2][4][4] = {};

    for (int k0 = 0; k0 < HDIM; k0 += 32) {
        #pragma unroll
        for (int it = 0; it < 4; it++) {
            float4 v = *(const float4*)(x + (size_t)(m0 + arow + it * 16) * HDIM + k0 + ac4 * 4);
            v.x = to_tf32(v.x); v.y = to_tf32(v.y);
            v.z = to_tf32(v.z); v.w = to_tf32(v.w);
            *(float4*)&As[arow + it * 16][ac4 * 4] = v;
        }
        #pragma unroll
        for (int it = 0; it < 4; it++) {
            int cc = (bc4 + it * 4) * 4;
            float4 vg = *(const float4*)(wsg + (size_t)(k0 + bkr) * ISDIM + n0 + cc);
            float4 vu = *(const float4*)(wsu + (size_t)(k0 + bkr) * ISDIM + n0 + cc);
            vg.x = to_tf32(vg.x); vg.y = to_tf32(vg.y); vg.z = to_tf32(vg.z); vg.w = to_tf32(vg.w);
            vu.x = to_tf32(vu.x); vu.y = to_tf32(vu.y); vu.z = to_tf32(vu.z); vu.w = to_tf32(vu.w);
            *(float4*)&Bgs[bkr][cc] = vg;
            *(float4*)&Bus[bkr][cc] = vu;
        }
        __syncthreads();
        #pragma unroll
        for (int ks = 0; ks < 32; ks += 8) {
            float a[2][4];
            #pragma unroll
            for (int mt = 0; mt < 2; mt++) {
                int rb = wm + mt * 16 + r;
                a[mt][0] = As[rb][ks + c];
                a[mt][1] = As[rb + 8][ks + c];
                a[mt][2] = As[rb][ks + c + 4];
                a[mt][3] = As[rb + 8][ks + c + 4];
            }
            #pragma unroll
            for (int nt = 0; nt < 4; nt++) {
                int cb = wn + nt * 8 + r;
                float bg[2] = { Bgs[ks + c][cb], Bgs[ks + c + 4][cb] };
                float bu[2] = { Bus[ks + c][cb], Bus[ks + c + 4][cb] };
                #pragma unroll
                for (int mt = 0; mt < 2; mt++) {
                    mma_tf32(ag[mt][nt], a[mt], bg);
                    mma_tf32(au[mt][nt], a[mt], bu);
                }
            }
        }
        __syncthreads();
    }

    #pragma unroll
    for (int mt = 0; mt < 2; mt++) {
        int row0 = m0 + wm + mt * 16 + r;
        #pragma unroll
        for (int nt = 0; nt < 4; nt++) {
            int col = n0 + wn + nt * 8 + c * 2;
            float2 o0, o1;
            o0.x = silu(ag[mt][nt][0]) * au[mt][nt][0];
            o0.y = silu(ag[mt][nt][1]) * au[mt][nt][1];
            o1.x = silu(ag[mt][nt][2]) * au[mt][nt][2];
            o1.y = silu(ag[mt][nt][3]) * au[mt][nt][3];
            *(float2*)(g_acts + (size_t)row0 * ISDIM + col)       = o0;
            *(float2*)(g_acts + (size_t)(row0 + 8) * ISDIM + col) = o1;
        }
    }
}

// ---------------- kernel 4: expert down (M=count_e, N=1024, K=512) ----------
__global__ __launch_bounds__(128)
void down_expert_tc(const float* __restrict__ wd) {
    int e     = blockIdx.z;
    int count = g_counts[e];
    int m0    = blockIdx.y * 64;
    if (m0 >= count) return;
    int n0 = blockIdx.x * 64;

    const float* A = g_act + (size_t)e * T * IDIM;
    const float* B = wd    + (size_t)e * IDIM * HDIM;

    __shared__ float As[64][36];
    __shared__ float Bs[32][68];

    int tid = threadIdx.x, lane = tid & 31, warp = tid >> 5;
    int wm = (warp >> 1) * 32, wn = (warp & 1) * 32;
    int r = lane >> 2, c = lane & 3;

    int arow = tid >> 3, ac4 = tid & 7;
    int bkr = tid >> 2, bc4 = tid & 3;

    float acc[2][4][4] = {};

    for (int k0 = 0; k0 < IDIM; k0 += 32) {
        #pragma unroll
        for (int it = 0; it < 4; it++) {
            float4 v = *(const float4*)(A + (size_t)(m0 + arow + it * 16) * IDIM + k0 + ac4 * 4);
            v.x = to_tf32(v.x); v.y = to_tf32(v.y);
            v.z = to_tf32(v.z); v.w = to_tf32(v.w);
            *(float4*)&As[arow + it * 16][ac4 * 4] = v;
        }
        #pragma unroll
        for (int it = 0; it < 4; it++) {
            int cc = (bc4 + it * 4) * 4;
            float4 v = *(const float4*)(B + (size_t)(k0 + bkr) * HDIM + n0 + cc);
            v.x = to_tf32(v.x); v.y = to_tf32(v.y);
            v.z = to_tf32(v.z); v.w = to_tf32(v.w);
            *(float4*)&Bs[bkr][cc] = v;
        }
        __syncthreads();
        #pragma unroll
        for (int ks = 0; ks < 32; ks += 8) {
            float a[2][4];
            #pragma unroll
            for (int mt = 0; mt < 2; mt++) {
                int rb = wm + mt * 16 + r;
                a[mt][0] = As[rb][ks + c];
                a[mt][1] = As[rb + 8][ks + c];
                a[mt][2] = As[rb][ks + c + 4];
                a[mt][3] = As[rb + 8][ks + c + 4];
            }
            #pragma unroll
            for (int nt = 0; nt < 4; nt++) {
                int cb = wn + nt * 8 + r;
                float b[2] = { Bs[ks + c][cb], Bs[ks + c + 4][cb] };
                #pragma unroll
                for (int mt = 0; mt < 2; mt++)
                    mma_tf32(acc[mt][nt], a[mt], b);
            }
        }
        __syncthreads();
    }

    #pragma unroll
    for (int mt = 0; mt < 2; mt++) {
        int row0 = m0 + wm + mt * 16 + r;
        float w0 = (row0 < count)     ? g_wt[e * T + row0]     : 0.f;
        float w1 = (row0 + 8 < count) ? g_wt[e * T + row0 + 8] : 0.f;
        #pragma unroll
        for (int nt = 0; nt < 4; nt++) {
            int col = n0 + wn + nt * 8 + c * 2;
            if (row0 < count) {
                float2 o = { w0 * acc[mt][nt][0], w0 * acc[mt][nt][1] };
                *(float2*)(g_down + (size_t)(e * T + row0) * HDIM + col) = o;
            }
            if (row0 + 8 < count) {
                float2 o = { w1 * acc[mt][nt][2], w1 * acc[mt][nt][3] };
                *(float2*)(g_down + (size_t)(e * T + row0 + 8) * HDIM + col) = o;
            }
        }
    }
}

// ---------------- kernel 5: shared down + combine (M=1024, N=1024, K=2048) --
__global__ __launch_bounds__(128)
void shared_down_combine_tc(const float* __restrict__ wsd,
                            float* __restrict__ out) {
    int m0 = blockIdx.y * 64;
    int n0 = blockIdx.x * 64;

    __shared__ float As[64][36];
    __shared__ float Bs[32][68];

    int tid = threadIdx.x, lane = tid & 31, warp = tid >> 5;
    int wm = (warp >> 1) * 32, wn = (warp & 1) * 32;
    int r = lane >> 2, c = lane & 3;

    int arow = tid >> 3, ac4 = tid & 7;
    int bkr = tid >> 2, bc4 = tid & 3;

    float acc[2][4][4] = {};

    for (int k0 = 0; k0 < ISDIM; k0 += 32) {
        #pragma unroll
        for (int it = 0; it < 4; it++) {
            float4 v = *(const float4*)(g_acts + (size_t)(m0 + arow + it * 16) * ISDIM + k0 + ac4 * 4);
            v.x = to_tf32(v.x); v.y = to_tf32(v.y);
            v.z = to_tf32(v.z); v.w = to_tf32(v.w);
            *(float4*)&As[arow + it * 16][ac4 * 4] = v;
        }
        #pragma unroll
        for (int it = 0; it < 4; it++) {
            int cc = (bc4 + it * 4) * 4;
            float4 v = *(const float4*)(wsd + (size_t)(k0 + bkr) * HDIM + n0 + cc);
            v.x = to_tf32(v.x); v.y = to_tf32(v.y);
            v.z = to_tf32(v.z); v.w = to_tf32(v.w);
            *(float4*)&Bs[bkr][cc] = v;
        }
        __syncthreads();
        #pragma unroll
        for (int ks = 0; ks < 32; ks += 8) {
            float a[2][4];
            #pragma unroll
            for (int mt = 0; mt < 2; mt++) {
                int rb = wm + mt * 16 + r;
                a[mt][0] = As[rb][ks + c];
                a[mt][1] = As[rb + 8][ks + c];
                a[mt][2] = As[rb][ks + c + 4];
                a[mt][3] = As[rb + 8][ks + c + 4];
            }
            #pragma unroll
            for (int nt = 0; nt < 4; nt++) {
                int cb = wn + nt * 8 + r;
                float b[2] = { Bs[ks + c][cb], Bs[ks + c + 4][cb] };
                #pragma unroll
                for (int mt = 0; mt < 2; mt++)
                    mma_tf32(acc[mt][nt], a[mt], b);
            }
        }
        __syncthreads();
    }

    #pragma unroll
    for (int mt = 0; mt < 2; mt++) {
        #pragma unroll
        for (int half = 0; half < 2; half++) {
            int t = m0 + wm + mt * 16 + r + half * 8;
            float sg = g_sg[t];
            int s0 = g_slot[t * TOPK + 0];
            int s1 = g_slot[t * TOPK + 1];
            int s2 = g_slot[t * TOPK + 2];
            int s3 = g_slot[t * TOPK + 3];
            #pragma unroll
            for (int nt = 0; nt < 4; nt++) {
                int col = n0 + wn + nt * 8 + c * 2;
                float2 d0 = *(const float2*)(g_down + (size_t)s0 * HDIM + col);
                float2 d1 = *(const float2*)(g_down + (size_t)s1 * HDIM + col);
                float2 d2 = *(const float2*)(g_down + (size_t)s2 * HDIM + col);
                float2 d3 = *(const float2*)(g_down + (size_t)s3 * HDIM + col);
                float ax = acc[mt][nt][half * 2 + 0];
                float ay = acc[mt][nt][half * 2 + 1];
                float2 o;
                o.x = sg * ax + d0.x + d1.x + d2.x + d3.x;
                o.y = sg * ay + d0.y + d1.y + d2.y + d3.y;
                *(float2*)(out + (size_t)t * HDIM + col) = o;
            }
        }
    }
}

// ---------------- launch -----------------------------------------------------
extern "C" void kernel_launch(void* const* d_in, const int* in_sizes, int n_in,
                              void* d_out, int out_size) {
    const float* x    = (const float*)d_in[0];   // [1,1024,1024]
    const float* wr   = (const float*)d_in[1];   // [1024,16]
    const float* wg   = (const float*)d_in[2];   // [16,1024,512]
    const float* wu   = (const float*)d_in[3];   // [16,1024,512]
    const float* wd   = (const float*)d_in[4];   // [16,512,1024]
    const float* wsg  = (const float*)d_in[5];   // [1024,2048]
    const float* wsu  = (const float*)d_in[6];   // [1024,2048]
    const float* wsd  = (const float*)d_in[7];   // [2048,1024]
    const float* wshg = (const float*)d_in[8];   // [1024,1]
    float* out = (float*)d_out;                  // [out (T*H) | router_logits (T*E)]

    zero_counts_kernel<<<1, 32>>>();
    router_kernel<<<T, 512>>>(x, wr, wshg, out + (size_t)T * HDIM);
    gateup_expert_tc<<<dim3(IDIM / 64, T / 64, NEXP), 128>>>(x, wg, wu);
    gateup_shared_tc<<<dim3(ISDIM / 64, T / 64), 128>>>(x, wsg, wsu);
    down_expert_tc<<<dim3(HDIM / 64, T / 64, NEXP), 128>>>(wd);
    shared_down_combine_tc<<<dim3(HDIM / 64, T / 64), 128>>>(wsd, out);
}

// round 3
// speedup vs baseline: 2.0299x; 1.0737x over previous
#include <cuda_runtime.h>
#include <cuda_bf16.h>
#include <math.h>

#define T     1024
#define HDIM  1024
#define NEXP  16
#define IDIM  512
#define ISDIM 2048
#define TOPK  4

// ---------------- scratch (device globals; no allocation allowed) ----------
__device__ int   g_counts[NEXP];
__device__ int   g_tok[NEXP * T];
__device__ float g_wt[NEXP * T];
__device__ int   g_slot[T * TOPK];
__device__ float g_sg[T];
__device__ float g_act[(size_t)NEXP * T * IDIM];
__device__ float g_acts[(size_t)T * ISDIM];
__device__ float g_down[(size_t)NEXP * T * HDIM];

// ---------------- helpers ----------------------------------------------------
__device__ __forceinline__ float to_tf32(float x) {
    unsigned u;
    asm("cvt.rna.tf32.f32 %0, %1;" : "=r"(u) : "f"(x));
    return __uint_as_float(u);
}
__device__ __forceinline__ float4 cvt4(float4 v) {
    v.x = to_tf32(v.x); v.y = to_tf32(v.y);
    v.z = to_tf32(v.z); v.w = to_tf32(v.w);
    return v;
}
__device__ __forceinline__ void mma_tf32(float* d, const float* a, const float* b) {
    asm volatile(
        "mma.sync.aligned.m16n8k8.row.col.f32.tf32.tf32.f32 "
        "{%0,%1,%2,%3}, {%4,%5,%6,%7}, {%8,%9}, {%0,%1,%2,%3};\n"
        : "+f"(d[0]), "+f"(d[1]), "+f"(d[2]), "+f"(d[3])
        : "r"(__float_as_uint(a[0])), "r"(__float_as_uint(a[1])),
          "r"(__float_as_uint(a[2])), "r"(__float_as_uint(a[3])),
          "r"(__float_as_uint(b[0])), "r"(__float_as_uint(b[1])));
}
__device__ __forceinline__ float silu(float g) { return g / (1.f + expf(-g)); }

// ---------------- kernel 0: zero counts ------------------------------------
__global__ void zero_counts_kernel() {
    if (threadIdx.x < NEXP) g_counts[threadIdx.x] = 0;
}

// ---------------- kernel 1: router ------------------------------------------
__global__ void router_kernel(const float* __restrict__ x,
                              const float* __restrict__ wr,
                              const float* __restrict__ wsg,
                              float* __restrict__ logits_out) {
    int t    = blockIdx.x;
    int warp = threadIdx.x >> 5;
    int lane = threadIdx.x & 31;
    __shared__ float s_logit[NEXP];

    const float* xr = x + (size_t)t * HDIM;

    {
        float acc = 0.f;
        for (int h = lane; h < HDIM; h += 32)
            acc += xr[h] * wr[h * NEXP + warp];
        #pragma unroll
        for (int o = 16; o; o >>= 1) acc += __shfl_xor_sync(0xffffffffu, acc, o);
        if (lane == 0) {
            s_logit[warp] = acc;
            logits_out[t * NEXP + warp] = acc;
        }
    }
    if (warp == 0) {
        float acc = 0.f;
        for (int h = lane; h < HDIM; h += 32) acc += xr[h] * wsg[h];
        #pragma unroll
        for (int o = 16; o; o >>= 1) acc += __shfl_xor_sync(0xffffffffu, acc, o);
        if (lane == 0) g_sg[t] = 1.f / (1.f + expf(-acc));
    }
    __syncthreads();

    if (threadIdx.x == 0) {
        float p[NEXP];
        float mx = -1e30f;
        #pragma unroll
        for (int e = 0; e < NEXP; e++) mx = fmaxf(mx, s_logit[e]);
        float sum = 0.f;
        #pragma unroll
        for (int e = 0; e < NEXP; e++) { p[e] = expf(s_logit[e] - mx); sum += p[e]; }
        float inv = 1.f / sum;
        #pragma unroll
        for (int e = 0; e < NEXP; e++) p[e] *= inv;

        int   idx[TOPK];
        float w[TOPK];
        float wsum = 0.f;
        #pragma unroll
        for (int k = 0; k < TOPK; k++) {
            int best = 0; float bv = -1.f;
            #pragma unroll
            for (int e = 0; e < NEXP; e++)
                if (p[e] > bv) { bv = p[e]; best = e; }
            idx[k] = best; w[k] = bv; wsum += bv; p[best] = -2.f;
        }
        float winv = 1.f / wsum;
        #pragma unroll
        for (int k = 0; k < TOPK; k++) {
            int e = idx[k];
            int pos = atomicAdd(&g_counts[e], 1);
            g_tok[e * T + pos] = t;
            g_wt[e * T + pos]  = w[k] * winv;
            g_slot[t * TOPK + k] = e * T + pos;
        }
    }
}

// ============================================================================
// TF32 GEMMs. 128 threads = 4 warps in 2x2; warp tile 32x32 (2 x 4 m16n8k8).
// Bs stride 72 (== 8 mod 32) -> conflict-free B fragment LDS.
// Register-prefetch + double-buffered smem -> 1 sync / k-tile, LDG overlapped.
// ============================================================================

// ---------------- kernel 2: expert gate/up fused, BK=16 ---------------------
__global__ __launch_bounds__(128)
void gateup_expert_tc(const float* __restrict__ x,
                      const float* __restrict__ wg,
                      const float* __restrict__ wu) {
    int e     = blockIdx.z;
    int count = g_counts[e];
    int m0    = blockIdx.y * 64;
    if (m0 >= count) return;
    int n0 = blockIdx.x * 64;

    const float* Bgp = wg + (size_t)e * HDIM * IDIM;
    const float* Bup = wu + (size_t)e * HDIM * IDIM;

    __shared__ float As [2][64][20];
    __shared__ float Bgs[2][16][72];
    __shared__ float Bus[2][16][72];

    int tid = threadIdx.x, lane = tid & 31, warp = tid >> 5;
    int wm = (warp >> 1) * 32, wn = (warp & 1) * 32;
    int r = lane >> 2, c = lane & 3;

    int ar = tid >> 1, ak = (tid & 1) * 8;       // A: row, col-half
    int br = tid >> 3, bc = (tid & 7) * 8;       // B: row, col-group

    int row = m0 + ar;
    const float* arow = (row < count) ? (x + (size_t)g_tok[e * T + row] * HDIM)
                                      : nullptr;

    float4 pa0, pa1, pg0, pg1, pu0, pu1;
    #define GU_LD(K0) do {                                                     \
        pa0 = arow ? *(const float4*)(arow + (K0) + ak)                        \
                   : make_float4(0.f,0.f,0.f,0.f);                             \
        pa1 = arow ? *(const float4*)(arow + (K0) + ak + 4)                    \
                   : make_float4(0.f,0.f,0.f,0.f);                             \
        pg0 = *(const float4*)(Bgp + (size_t)((K0) + br) * IDIM + n0 + bc);    \
        pg1 = *(const float4*)(Bgp + (size_t)((K0) + br) * IDIM + n0 + bc + 4);\
        pu0 = *(const float4*)(Bup + (size_t)((K0) + br) * IDIM + n0 + bc);    \
        pu1 = *(const float4*)(Bup + (size_t)((K0) + br) * IDIM + n0 + bc + 4);\
    } while (0)
    #define GU_ST(B) do {                                                      \
        *(float4*)&As [B][ar][ak]     = cvt4(pa0);                             \
        *(float4*)&As [B][ar][ak + 4] = cvt4(pa1);                             \
        *(float4*)&Bgs[B][br][bc]     = cvt4(pg0);                             \
        *(float4*)&Bgs[B][br][bc + 4] = cvt4(pg1);                             \
        *(float4*)&Bus[B][br][bc]     = cvt4(pu0);                             \
        *(float4*)&Bus[B][br][bc + 4] = cvt4(pu1);                             \
    } while (0)

    float ag[2][4][4] = {};
    float au[2][4][4] = {};

    GU_LD(0); GU_ST(0);
    const int NT = HDIM / 16;
    for (int kt = 0; kt < NT; kt++) {
        __syncthreads();
        if (kt + 1 < NT) GU_LD((kt + 1) * 16);
        int b = kt & 1;
        #pragma unroll
        for (int ks = 0; ks < 16; ks += 8) {
            float a[2][4];
            #pragma unroll
            for (int mt = 0; mt < 2; mt++) {
                int rb = wm + mt * 16 + r;
                a[mt][0] = As[b][rb][ks + c];
                a[mt][1] = As[b][rb + 8][ks + c];
                a[mt][2] = As[b][rb][ks + c + 4];
                a[mt][3] = As[b][rb + 8][ks + c + 4];
            }
            #pragma unroll
            for (int nt = 0; nt < 4; nt++) {
                int cb = wn + nt * 8 + r;
                float bg[2] = { Bgs[b][ks + c][cb], Bgs[b][ks + c + 4][cb] };
                float bu[2] = { Bus[b][ks + c][cb], Bus[b][ks + c + 4][cb] };
                #pragma unroll
                for (int mt = 0; mt < 2; mt++) {
                    mma_tf32(ag[mt][nt], a[mt], bg);
                    mma_tf32(au[mt][nt], a[mt], bu);
                }
            }
        }
        if (kt + 1 < NT) GU_ST((kt + 1) & 1);
    }

    float* Cb = g_act + (size_t)e * T * IDIM;
    #pragma unroll
    for (int mt = 0; mt < 2; mt++) {
        int row0 = m0 + wm + mt * 16 + r;
        #pragma unroll
        for (int nt = 0; nt < 4; nt++) {
            int col = n0 + wn + nt * 8 + c * 2;
            if (row0 < count) {
                float2 o;
                o.x = silu(ag[mt][nt][0]) * au[mt][nt][0];
                o.y = silu(ag[mt][nt][1]) * au[mt][nt][1];
                *(float2*)(Cb + (size_t)row0 * IDIM + col) = o;
            }
            if (row0 + 8 < count) {
                float2 o;
                o.x = silu(ag[mt][nt][2]) * au[mt][nt][2];
                o.y = silu(ag[mt][nt][3]) * au[mt][nt][3];
                *(float2*)(Cb + (size_t)(row0 + 8) * IDIM + col) = o;
            }
        }
    }
}

// ---------------- kernel 3: shared gate/up, BK=16 ---------------------------
__global__ __launch_bounds__(128)
void gateup_shared_tc(const float* __restrict__ x,
                      const float* __restrict__ wsg,
                      const float* __restrict__ wsu) {
    int m0 = blockIdx.y * 64;
    int n0 = blockIdx.x * 64;

    __shared__ float As [2][64][20];
    __shared__ float Bgs[2][16][72];
    __shared__ float Bus[2][16][72];

    int tid = threadIdx.x, lane = tid & 31, warp = tid >> 5;
    int wm = (warp >> 1) * 32, wn = (warp & 1) * 32;
    int r = lane >> 2, c = lane & 3;

    int ar = tid >> 1, ak = (tid & 1) * 8;
    int br = tid >> 3, bc = (tid & 7) * 8;

    const float* arow = x + (size_t)(m0 + ar) * HDIM;

    float4 pa0, pa1, pg0, pg1, pu0, pu1;
    #define GS_LD(K0) do {                                                      \
        pa0 = *(const float4*)(arow + (K0) + ak);                               \
        pa1 = *(const float4*)(arow + (K0) + ak + 4);                           \
        pg0 = *(const float4*)(wsg + (size_t)((K0) + br) * ISDIM + n0 + bc);    \
        pg1 = *(const float4*)(wsg + (size_t)((K0) + br) * ISDIM + n0 + bc + 4);\
        pu0 = *(const float4*)(wsu + (size_t)((K0) + br) * ISDIM + n0 + bc);    \
        pu1 = *(const float4*)(wsu + (size_t)((K0) + br) * ISDIM + n0 + bc + 4);\
    } while (0)

    float ag[2][4][4] = {};
    float au[2][4][4] = {};

    GS_LD(0); GU_ST(0);
    const int NT = HDIM / 16;
    for (int kt = 0; kt < NT; kt++) {
        __syncthreads();
        if (kt + 1 < NT) GS_LD((kt + 1) * 16);
        int b = kt & 1;
        #pragma unroll
        for (int ks = 0; ks < 16; ks += 8) {
            float a[2][4];
            #pragma unroll
            for (int mt = 0; mt < 2; mt++) {
                int rb = wm + mt * 16 + r;
                a[mt][0] = As[b][rb][ks + c];
                a[mt][1] = As[b][rb + 8][ks + c];
                a[mt][2] = As[b][rb][ks + c + 4];
                a[mt][3] = As[b][rb + 8][ks + c + 4];
            }
            #pragma unroll
            for (int nt = 0; nt < 4; nt++) {
                int cb = wn + nt * 8 + r;
                float bg[2] = { Bgs[b][ks + c][cb], Bgs[b][ks + c + 4][cb] };
                float bu[2] = { Bus[b][ks + c][cb], Bus[b][ks + c + 4][cb] };
                #pragma unroll
                for (int mt = 0; mt < 2; mt++) {
                    mma_tf32(ag[mt][nt], a[mt], bg);
                    mma_tf32(au[mt][nt], a[mt], bu);
                }
            }
        }
        if (kt + 1 < NT) GU_ST((kt + 1) & 1);
    }

    #pragma unroll
    for (int mt = 0; mt < 2; mt++) {
        int row0 = m0 + wm + mt * 16 + r;
        #pragma unroll
        for (int nt = 0; nt < 4; nt++) {
            int col = n0 + wn + nt * 8 + c * 2;
            float2 o0, o1;
            o0.x = silu(ag[mt][nt][0]) * au[mt][nt][0];
            o0.y = silu(ag[mt][nt][1]) * au[mt][nt][1];
            o1.x = silu(ag[mt][nt][2]) * au[mt][nt][2];
            o1.y = silu(ag[mt][nt][3]) * au[mt][nt][3];
            *(float2*)(g_acts + (size_t)row0 * ISDIM + col)       = o0;
            *(float2*)(g_acts + (size_t)(row0 + 8) * ISDIM + col) = o1;
        }
    }
}

// ---------------- kernel 4: expert down, BK=32 ------------------------------
__global__ __launch_bounds__(128)
void down_expert_tc(const float* __restrict__ wd) {
    int e     = blockIdx.z;
    int count = g_counts[e];
    int m0    = blockIdx.y * 64;
    if (m0 >= count) return;
    int n0 = blockIdx.x * 64;

    const float* A = g_act + (size_t)e * T * IDIM;
    const float* B = wd    + (size_t)e * IDIM * HDIM;

    __shared__ float As[2][64][36];
    __shared__ float Bs[2][32][72];

    int tid = threadIdx.x, lane = tid & 31, warp = tid >> 5;
    int wm = (warp >> 1) * 32, wn = (warp & 1) * 32;
    int r = lane >> 2, c = lane & 3;

    int ar = tid >> 1, ak = (tid & 1) * 16;
    int br = tid >> 2, bc = (tid & 3) * 16;

    const float* arow = A + (size_t)(m0 + ar) * IDIM;

    float4 pa[4], pb[4];
    #define DN_LD(BASE_B, LDB, K0) do {                                          \
        _Pragma("unroll")                                                        \
        for (int i = 0; i < 4; i++) {                                            \
            pa[i] = *(const float4*)(arow + (K0) + ak + i * 4);                  \
            pb[i] = *(const float4*)((BASE_B) + (size_t)((K0) + br) * (LDB)      \
                                     + n0 + bc + i * 4);                         \
        }                                                                        \
    } while (0)
    #define DN_ST(BUF) do {                                                      \
        _Pragma("unroll")                                                        \
        for (int i = 0; i < 4; i++) {                                            \
            *(float4*)&As[BUF][ar][ak + i * 4] = cvt4(pa[i]);                    \
            *(float4*)&Bs[BUF][br][bc + i * 4] = cvt4(pb[i]);                    \
        }                                                                        \
    } while (0)

    float acc[2][4][4] = {};

    DN_LD(B, HDIM, 0); DN_ST(0);
    const int NT = IDIM / 32;
    for (int kt = 0; kt < NT; kt++) {
        __syncthreads();
        if (kt + 1 < NT) DN_LD(B, HDIM, (kt + 1) * 32);
        int b = kt & 1;
        #pragma unroll
        for (int ks = 0; ks < 32; ks += 8) {
            float a[2][4];
            #pragma unroll
            for (int mt = 0; mt < 2; mt++) {
                int rb = wm + mt * 16 + r;
                a[mt][0] = As[b][rb][ks + c];
                a[mt][1] = As[b][rb + 8][ks + c];
                a[mt][2] = As[b][rb][ks + c + 4];
                a[mt][3] = As[b][rb + 8][ks + c + 4];
            }
            #pragma unroll
            for (int nt = 0; nt < 4; nt++) {
                int cb = wn + nt * 8 + r;
                float bb[2] = { Bs[b][ks + c][cb], Bs[b][ks + c + 4][cb] };
                #pragma unroll
                for (int mt = 0; mt < 2; mt++)
                    mma_tf32(acc[mt][nt], a[mt], bb);
            }
        }
        if (kt + 1 < NT) DN_ST((kt + 1) & 1);
    }

    #pragma unroll
    for (int mt = 0; mt < 2; mt++) {
        int row0 = m0 + wm + mt * 16 + r;
        float w0 = (row0 < count)     ? g_wt[e * T + row0]     : 0.f;
        float w1 = (row0 + 8 < count) ? g_wt[e * T + row0 + 8] : 0.f;
        #pragma unroll
        for (int nt = 0; nt < 4; nt++) {
            int col = n0 + wn + nt * 8 + c * 2;
            if (row0 < count) {
                float2 o = { w0 * acc[mt][nt][0], w0 * acc[mt][nt][1] };
                *(float2*)(g_down + (size_t)(e * T + row0) * HDIM + col) = o;
            }
            if (row0 + 8 < count) {
                float2 o = { w1 * acc[mt][nt][2], w1 * acc[mt][nt][3] };
                *(float2*)(g_down + (size_t)(e * T + row0 + 8) * HDIM + col) = o;
            }
        }
    }
}

// ---------------- kernel 5: shared down + combine, BK=32 --------------------
__global__ __launch_bounds__(128)
void shared_down_combine_tc(const float* __restrict__ wsd,
                            float* __restrict__ out) {
    int m0 = blockIdx.y * 64;
    int n0 = blockIdx.x * 64;

    __shared__ float As[2][64][36];
    __shared__ float Bs[2][32][72];

    int tid = threadIdx.x, lane = tid & 31, warp = tid >> 5;
    int wm = (warp >> 1) * 32, wn = (warp & 1) * 32;
    int r = lane >> 2, c = lane & 3;

    int ar = tid >> 1, ak = (tid & 1) * 16;
    int br = tid >> 2, bc = (tid & 3) * 16;

    const float* arow = g_acts + (size_t)(m0 + ar) * ISDIM;

    float4 pa[4], pb[4];
    float acc[2][4][4] = {};

    DN_LD(wsd, HDIM, 0); DN_ST(0);
    const int NT = ISDIM / 32;
    for (int kt = 0; kt < NT; kt++) {
        __syncthreads();
        if (kt + 1 < NT) DN_LD(wsd, HDIM, (kt + 1) * 32);
        int b = kt & 1;
        #pragma unroll
        for (int ks = 0; ks < 32; ks += 8) {
            float a[2][4];
            #pragma unroll
            for (int mt = 0; mt < 2; mt++) {
                int rb = wm + mt * 16 + r;
                a[mt][0] = As[b][rb][ks + c];
                a[mt][1] = As[b][rb + 8][ks + c];
                a[mt][2] = As[b][rb][ks + c + 4];
                a[mt][3] = As[b][rb + 8][ks + c + 4];
            }
            #pragma unroll
            for (int nt = 0; nt < 4; nt++) {
                int cb = wn + nt * 8 + r;
                float bb[2] = { Bs[b][ks + c][cb], Bs[b][ks + c + 4][cb] };
                #pragma unroll
                for (int mt = 0; mt < 2; mt++)
                    mma_tf32(acc[mt][nt], a[mt], bb);
            }
        }
        if (kt + 1 < NT) DN_ST((kt + 1) & 1);
    }

    #pragma unroll
    for (int mt = 0; mt < 2; mt++) {
        #pragma unroll
        for (int half = 0; half < 2; half++) {
            int t = m0 + wm + mt * 16 + r + half * 8;
            float sg = g_sg[t];
            int s0 = g_slot[t * TOPK + 0];
            int s1 = g_slot[t * TOPK + 1];
            int s2 = g_slot[t * TOPK + 2];
            int s3 = g_slot[t * TOPK + 3];
            #pragma unroll
            for (int nt = 0; nt < 4; nt++) {
                int col = n0 + wn + nt * 8 + c * 2;
                float2 d0 = *(const float2*)(g_down + (size_t)s0 * HDIM + col);
                float2 d1 = *(const float2*)(g_down + (size_t)s1 * HDIM + col);
                float2 d2 = *(const float2*)(g_down + (size_t)s2 * HDIM + col);
                float2 d3 = *(const float2*)(g_down + (size_t)s3 * HDIM + col);
                float ax = acc[mt][nt][half * 2 + 0];
                float ay = acc[mt][nt][half * 2 + 1];
                float2 o;
                o.x = sg * ax + d0.x + d1.x + d2.x + d3.x;
                o.y = sg * ay + d0.y + d1.y + d2.y + d3.y;
                *(float2*)(out + (size_t)t * HDIM + col) = o;
            }
        }
    }
}

// ---------------- launch -----------------------------------------------------
extern "C" void kernel_launch(void* const* d_in, const int* in_sizes, int n_in,
                              void* d_out, int out_size) {
    const float* x    = (const float*)d_in[0];
    const float* wr   = (const float*)d_in[1];
    const float* wg   = (const float*)d_in[2];
    const float* wu   = (const float*)d_in[3];
    const float* wd   = (const float*)d_in[4];
    const float* wsg  = (const float*)d_in[5];
    const float* wsu  = (const float*)d_in[6];
    const float* wsd  = (const float*)d_in[7];
    const float* wshg = (const float*)d_in[8];
    float* out = (float*)d_out;

    zero_counts_kernel<<<1, 32>>>();
    router_kernel<<<T, 512>>>(x, wr, wshg, out + (size_t)T * HDIM);
    gateup_expert_tc<<<dim3(IDIM / 64, T / 64, NEXP), 128>>>(x, wg, wu);
    gateup_shared_tc<<<dim3(ISDIM / 64, T / 64), 128>>>(x, wsg, wsu);
    down_expert_tc<<<dim3(HDIM / 64, T / 64, NEXP), 128>>>(wd);
    shared_down_combine_tc<<<dim3(HDIM / 64, T / 64), 128>>>(wsd, out);
}